// round 1
// baseline (speedup 1.0000x reference)
#include <cuda_runtime.h>
#include <cuda_bf16.h>
#include <math.h>
#include <limits.h>

#define NN 50000
#define EE 800000
#define MM 3
#define IN_ 256
#define HID_ 16
#define HEADS_ 8
#define HD_ 128          // HEADS_*HID_
#define OUT_ 8

// ---------------- scratch (static device memory; no allocs) ----------------
__device__ float g_feat[MM * NN * HD_];      // per-path projected features
__device__ float g_z[MM * NN * HD_];         // message accumulators -> elu'd z
__device__ float g_el[MM * NN * HEADS_];
__device__ float g_er[MM * NN * HEADS_];
__device__ int   g_emax[MM * NN * HEADS_];   // ordered-int encoded float max
__device__ float g_denom[MM * NN * HEADS_];
__device__ float g_w[MM * NN];               // structure-attention scores
__device__ int   g_wmax[MM];
__device__ float g_wsum[MM];
__device__ float g_pz[MM * HD_];             // sum_n exp(w-wmax) * z

// monotone float<->int encoding for atomicMax on floats
__device__ __forceinline__ int enc_f(float f) {
    int i = __float_as_int(f);
    return i < 0 ? (i ^ 0x7fffffff) : i;
}
__device__ __forceinline__ float dec_i(int i) {
    return __int_as_float(i < 0 ? (i ^ 0x7fffffff) : i);
}

// ---------------- init ----------------
__global__ void k_init() {
    int idx = blockIdx.x * blockDim.x + threadIdx.x;
    int tot = MM * NN * HEADS_;
    for (int i = idx; i < tot; i += gridDim.x * blockDim.x) g_emax[i] = INT_MIN;
    if (idx < MM) g_wmax[idx] = INT_MIN;
}

// ---------------- GEMM: feat = h @ fc_w[p], fused el/er epilogue ----------------
// grid: (ceil(NN/32), MM), block 256. Tile: 32 rows x 128 cols, K chunk 32.
__global__ void k_gemm(const float* __restrict__ h, const float* __restrict__ W,
                       const float* __restrict__ al, const float* __restrict__ ar) {
    __shared__ float  As[32][33];
    __shared__ float4 Bs[32][32];
    int p = blockIdx.y;
    int row0 = blockIdx.x * 32;
    int tid = threadIdx.x;
    int cx = tid & 31;   // float4 column group (cols 4cx..4cx+3)
    int ry = tid >> 5;   // warp id == row group (rows ry*4..ry*4+3)
    const float* Wp = W + (size_t)p * IN_ * HD_;

    float acc[4][4];
#pragma unroll
    for (int i = 0; i < 4; i++)
#pragma unroll
        for (int j = 0; j < 4; j++) acc[i][j] = 0.f;

    for (int kk = 0; kk < IN_; kk += 32) {
        // A: 32x32 chunk, each thread one float4
        {
            int r = tid >> 3;
            int k4 = (tid & 7) * 4;
            float4 av = make_float4(0.f, 0.f, 0.f, 0.f);
            if (row0 + r < NN)
                av = *(const float4*)&h[(size_t)(row0 + r) * IN_ + kk + k4];
            As[r][k4 + 0] = av.x; As[r][k4 + 1] = av.y;
            As[r][k4 + 2] = av.z; As[r][k4 + 3] = av.w;
        }
        // B: 32x128 chunk as float4
#pragma unroll
        for (int j = 0; j < 4; j++) {
            int q = tid + 256 * j;
            int bk = q >> 5, bc = q & 31;
            Bs[bk][bc] = *(const float4*)&Wp[(size_t)(kk + bk) * HD_ + bc * 4];
        }
        __syncthreads();
#pragma unroll
        for (int k = 0; k < 32; k++) {
            float a0 = As[ry * 4 + 0][k];
            float a1 = As[ry * 4 + 1][k];
            float a2 = As[ry * 4 + 2][k];
            float a3 = As[ry * 4 + 3][k];
            float4 b = Bs[k][cx];
            acc[0][0] += a0 * b.x; acc[0][1] += a0 * b.y; acc[0][2] += a0 * b.z; acc[0][3] += a0 * b.w;
            acc[1][0] += a1 * b.x; acc[1][1] += a1 * b.y; acc[1][2] += a1 * b.z; acc[1][3] += a1 * b.w;
            acc[2][0] += a2 * b.x; acc[2][1] += a2 * b.y; acc[2][2] += a2 * b.z; acc[2][3] += a2 * b.w;
            acc[3][0] += a3 * b.x; acc[3][1] += a3 * b.y; acc[3][2] += a3 * b.z; acc[3][3] += a3 * b.w;
        }
        __syncthreads();
    }

    int head = cx >> 2;
    int dbase = (cx * 4) & 15;
    // attn vectors for this thread's 4 columns (constant across rows)
    float av0 = al[(size_t)p * HEADS_ * HID_ + head * HID_ + dbase + 0];
    float av1 = al[(size_t)p * HEADS_ * HID_ + head * HID_ + dbase + 1];
    float av2 = al[(size_t)p * HEADS_ * HID_ + head * HID_ + dbase + 2];
    float av3 = al[(size_t)p * HEADS_ * HID_ + head * HID_ + dbase + 3];
    float rv0 = ar[(size_t)p * HEADS_ * HID_ + head * HID_ + dbase + 0];
    float rv1 = ar[(size_t)p * HEADS_ * HID_ + head * HID_ + dbase + 1];
    float rv2 = ar[(size_t)p * HEADS_ * HID_ + head * HID_ + dbase + 2];
    float rv3 = ar[(size_t)p * HEADS_ * HID_ + head * HID_ + dbase + 3];

#pragma unroll
    for (int i = 0; i < 4; i++) {
        int row = row0 + ry * 4 + i;
        if (row < NN) {
            *(float4*)&g_feat[((size_t)p * NN + row) * HD_ + cx * 4] =
                make_float4(acc[i][0], acc[i][1], acc[i][2], acc[i][3]);
        }
        float pl = acc[i][0] * av0 + acc[i][1] * av1 + acc[i][2] * av2 + acc[i][3] * av3;
        float pr = acc[i][0] * rv0 + acc[i][1] * rv1 + acc[i][2] * rv2 + acc[i][3] * rv3;
        pl += __shfl_xor_sync(0xffffffffu, pl, 1);
        pl += __shfl_xor_sync(0xffffffffu, pl, 2);
        pr += __shfl_xor_sync(0xffffffffu, pr, 1);
        pr += __shfl_xor_sync(0xffffffffu, pr, 2);
        if ((cx & 3) == 0 && row < NN) {
            g_el[((size_t)p * NN + row) * HEADS_ + head] = pl;
            g_er[((size_t)p * NN + row) * HEADS_ + head] = pr;
        }
    }
}

// ---------------- edge pass 1: segment max ----------------
__global__ void k_edge_max(const int* __restrict__ edges) {
    int idx = blockIdx.x * blockDim.x + threadIdx.x;
    if (idx >= MM * EE) return;
    int p = idx / EE, e = idx - p * EE;
    const int* eb = edges + (size_t)p * 2 * EE;
    int src = eb[e], dst = eb[EE + e];
    const float* elp = &g_el[((size_t)p * NN + src) * HEADS_];
    const float* erp = &g_er[((size_t)p * NN + dst) * HEADS_];
    int* mx = &g_emax[((size_t)p * NN + dst) * HEADS_];
#pragma unroll
    for (int h2 = 0; h2 < HEADS_; h2++) {
        float v = elp[h2] + erp[h2];
        v = v > 0.f ? v : 0.2f * v;
        atomicMax(&mx[h2], enc_f(v));
    }
}

// ---------------- edge pass 2: segment sum of exp ----------------
__global__ void k_edge_sum(const int* __restrict__ edges) {
    int idx = blockIdx.x * blockDim.x + threadIdx.x;
    if (idx >= MM * EE) return;
    int p = idx / EE, e = idx - p * EE;
    const int* eb = edges + (size_t)p * 2 * EE;
    int src = eb[e], dst = eb[EE + e];
    const float* elp = &g_el[((size_t)p * NN + src) * HEADS_];
    const float* erp = &g_er[((size_t)p * NN + dst) * HEADS_];
    const int* mx = &g_emax[((size_t)p * NN + dst) * HEADS_];
    float* dn = &g_denom[((size_t)p * NN + dst) * HEADS_];
#pragma unroll
    for (int h2 = 0; h2 < HEADS_; h2++) {
        float v = elp[h2] + erp[h2];
        v = v > 0.f ? v : 0.2f * v;
        atomicAdd(&dn[h2], expf(v - dec_i(mx[h2])));
    }
}

// ---------------- edge pass 3: weighted aggregation (1 warp / edge) ----------------
__global__ void k_edge_agg(const int* __restrict__ edges) {
    int gw = (blockIdx.x * blockDim.x + threadIdx.x) >> 5;
    int lane = threadIdx.x & 31;
    if (gw >= MM * EE) return;
    int p = gw / EE, e = gw - p * EE;
    const int* eb = edges + (size_t)p * 2 * EE;
    int src = eb[e], dst = eb[EE + e];
    int h2 = lane >> 2;
    size_t sb = (size_t)p * NN + src;
    size_t db = (size_t)p * NN + dst;
    float v = g_el[sb * HEADS_ + h2] + g_er[db * HEADS_ + h2];
    v = v > 0.f ? v : 0.2f * v;
    float alpha = expf(v - dec_i(g_emax[db * HEADS_ + h2])) / g_denom[db * HEADS_ + h2];
    float4 f = *(const float4*)&g_feat[sb * HD_ + lane * 4];
    float* o = &g_z[db * HD_ + lane * 4];
    asm volatile("red.global.add.v4.f32 [%0], {%1,%2,%3,%4};"
                 :: "l"(o), "f"(f.x * alpha), "f"(f.y * alpha),
                    "f"(f.z * alpha), "f"(f.w * alpha)
                 : "memory");
}

// ---------------- elu + structure-attention score w ----------------
// grid (NN, MM), block 128
__global__ void k_elu_w(const float* __restrict__ sa_w1, const float* __restrict__ sa_b1,
                        const float* __restrict__ sa_w2) {
    int n = blockIdx.x, m = blockIdx.y, j = threadIdx.x;
    __shared__ float zs[HD_];
    __shared__ float red[4];
    size_t base = ((size_t)m * NN + n) * HD_;
    float x = g_z[base + j];
    x = x > 0.f ? x : expm1f(x);
    g_z[base + j] = x;
    zs[j] = x;
    __syncthreads();
    float s = sa_b1[j];
#pragma unroll 8
    for (int k = 0; k < HD_; k++) s += zs[k] * sa_w1[(size_t)k * HD_ + j];
    float t = tanhf(s) * sa_w2[j];
#pragma unroll
    for (int off = 16; off; off >>= 1) t += __shfl_xor_sync(0xffffffffu, t, off);
    if ((j & 31) == 0) red[j >> 5] = t;
    __syncthreads();
    if (j == 0) {
        float w = red[0] + red[1] + red[2] + red[3];
        g_w[(size_t)m * NN + n] = w;
        atomicMax(&g_wmax[m], enc_f(w));
    }
}

// ---------------- softmax-over-nodes weighted sum (block partials) ----------------
#define NODES_PER_BLK 64
__global__ void k_beta() {
    int j = threadIdx.x;
    int n0 = blockIdx.x * NODES_PER_BLK;
    float acc[MM] = {0.f, 0.f, 0.f};
    float wsl[MM] = {0.f, 0.f, 0.f};
    float wmx[MM];
#pragma unroll
    for (int m = 0; m < MM; m++) wmx[m] = dec_i(g_wmax[m]);
    int n1 = n0 + NODES_PER_BLK;
    if (n1 > NN) n1 = NN;
    for (int n = n0; n < n1; n++) {
#pragma unroll
        for (int m = 0; m < MM; m++) {
            float pv = expf(g_w[(size_t)m * NN + n] - wmx[m]);
            acc[m] += pv * g_z[((size_t)m * NN + n) * HD_ + j];
            if (j == 0) wsl[m] += pv;
        }
    }
#pragma unroll
    for (int m = 0; m < MM; m++) {
        atomicAdd(&g_pz[m * HD_ + j], acc[m]);
        if (j == 0) atomicAdd(&g_wsum[m], wsl[m]);
    }
}

// ---------------- final projection ----------------
__global__ void k_final(const float* __restrict__ pred_w, const float* __restrict__ pred_b,
                        float* __restrict__ out) {
    int t = threadIdx.x;
    if (t < MM * OUT_) {
        int m = t / OUT_, o = t - m * OUT_;
        float inv = 1.f / g_wsum[m];
        float s = pred_b[o];
#pragma unroll 8
        for (int j = 0; j < HD_; j++)
            s += g_pz[m * HD_ + j] * inv * pred_w[(size_t)j * OUT_ + o];
        out[t] = s;
    }
}

// ---------------- launch ----------------
extern "C" void kernel_launch(void* const* d_in, const int* in_sizes, int n_in,
                              void* d_out, int out_size) {
    const float* h      = (const float*)d_in[0];
    const int*   edges  = (const int*)d_in[1];
    const float* fc_w   = (const float*)d_in[2];
    const float* attn_l = (const float*)d_in[3];
    const float* attn_r = (const float*)d_in[4];
    const float* sa_w1  = (const float*)d_in[5];
    const float* sa_b1  = (const float*)d_in[6];
    const float* sa_w2  = (const float*)d_in[7];
    const float* pred_w = (const float*)d_in[8];
    const float* pred_b = (const float*)d_in[9];
    float* out = (float*)d_out;

    void *pz, *pden, *pwsum, *ppz;
    cudaGetSymbolAddress(&pz, g_z);
    cudaGetSymbolAddress(&pden, g_denom);
    cudaGetSymbolAddress(&pwsum, g_wsum);
    cudaGetSymbolAddress(&ppz, g_pz);
    cudaMemsetAsync(pz, 0, sizeof(float) * (size_t)MM * NN * HD_);
    cudaMemsetAsync(pden, 0, sizeof(float) * (size_t)MM * NN * HEADS_);
    cudaMemsetAsync(pwsum, 0, sizeof(float) * MM);
    cudaMemsetAsync(ppz, 0, sizeof(float) * MM * HD_);
    k_init<<<1024, 256>>>();

    dim3 gg((NN + 31) / 32, MM);
    k_gemm<<<gg, 256>>>(h, fc_w, attn_l, attn_r);

    int et = MM * EE;
    k_edge_max<<<(et + 255) / 256, 256>>>(edges);
    k_edge_sum<<<(et + 255) / 256, 256>>>(edges);

    long long thr = (long long)et * 32;
    k_edge_agg<<<(int)((thr + 255) / 256), 256>>>(edges);

    dim3 ge(NN, MM);
    k_elu_w<<<ge, 128>>>(sa_w1, sa_b1, sa_w2);
    k_beta<<<(NN + NODES_PER_BLK - 1) / NODES_PER_BLK, 128>>>();
    k_final<<<1, 32>>>(pred_w, pred_b, out);
}

// round 2
// speedup vs baseline: 1.9807x; 1.9807x over previous
#include <cuda_runtime.h>
#include <cuda_bf16.h>
#include <math.h>
#include <limits.h>

#define NN 50000
#define EE 800000
#define MM 3
#define IN_ 256
#define HID_ 16
#define HEADS_ 8
#define HD_ 128
#define OUT_ 8
#define NTASK (MM * NN)
#define CAP 32

// ---------------- scratch ----------------
__device__ float g_feat[MM * NN * HD_];
__device__ float g_z[MM * NN * HD_];
__device__ float g_el[MM * NN * HEADS_];
__device__ float g_er[MM * NN * HEADS_];
__device__ int   g_deg[NTASK];
__device__ int   g_off[NTASK];
__device__ int   g_cur[NTASK];
__device__ int   g_csr[MM * EE];
__device__ float g_w[MM * NN];
__device__ float g_wsum[MM];
__device__ float g_pz[MM * HD_];

// ---------------- GEMM: feat = h @ fc_w[p], fused el/er epilogue ----------------
__global__ void k_gemm(const float* __restrict__ h, const float* __restrict__ W,
                       const float* __restrict__ al, const float* __restrict__ ar) {
    __shared__ float  As[32][33];
    __shared__ float4 Bs[32][32];
    int p = blockIdx.y;
    int row0 = blockIdx.x * 32;
    int tid = threadIdx.x;
    int cx = tid & 31;
    int ry = tid >> 5;
    const float* Wp = W + (size_t)p * IN_ * HD_;

    float acc[4][4];
#pragma unroll
    for (int i = 0; i < 4; i++)
#pragma unroll
        for (int j = 0; j < 4; j++) acc[i][j] = 0.f;

    for (int kk = 0; kk < IN_; kk += 32) {
        {
            int r = tid >> 3;
            int k4 = (tid & 7) * 4;
            float4 av = make_float4(0.f, 0.f, 0.f, 0.f);
            if (row0 + r < NN)
                av = *(const float4*)&h[(size_t)(row0 + r) * IN_ + kk + k4];
            As[r][k4 + 0] = av.x; As[r][k4 + 1] = av.y;
            As[r][k4 + 2] = av.z; As[r][k4 + 3] = av.w;
        }
#pragma unroll
        for (int j = 0; j < 4; j++) {
            int q = tid + 256 * j;
            int bk = q >> 5, bc = q & 31;
            Bs[bk][bc] = *(const float4*)&Wp[(size_t)(kk + bk) * HD_ + bc * 4];
        }
        __syncthreads();
#pragma unroll
        for (int k = 0; k < 32; k++) {
            float a0 = As[ry * 4 + 0][k];
            float a1 = As[ry * 4 + 1][k];
            float a2 = As[ry * 4 + 2][k];
            float a3 = As[ry * 4 + 3][k];
            float4 b = Bs[k][cx];
            acc[0][0] += a0 * b.x; acc[0][1] += a0 * b.y; acc[0][2] += a0 * b.z; acc[0][3] += a0 * b.w;
            acc[1][0] += a1 * b.x; acc[1][1] += a1 * b.y; acc[1][2] += a1 * b.z; acc[1][3] += a1 * b.w;
            acc[2][0] += a2 * b.x; acc[2][1] += a2 * b.y; acc[2][2] += a2 * b.z; acc[2][3] += a2 * b.w;
            acc[3][0] += a3 * b.x; acc[3][1] += a3 * b.y; acc[3][2] += a3 * b.z; acc[3][3] += a3 * b.w;
        }
        __syncthreads();
    }

    int head = cx >> 2;
    int dbase = (cx * 4) & 15;
    size_t ab = (size_t)p * HEADS_ * HID_ + head * HID_ + dbase;
    float av0 = al[ab + 0], av1 = al[ab + 1], av2 = al[ab + 2], av3 = al[ab + 3];
    float rv0 = ar[ab + 0], rv1 = ar[ab + 1], rv2 = ar[ab + 2], rv3 = ar[ab + 3];

#pragma unroll
    for (int i = 0; i < 4; i++) {
        int row = row0 + ry * 4 + i;
        if (row < NN) {
            *(float4*)&g_feat[((size_t)p * NN + row) * HD_ + cx * 4] =
                make_float4(acc[i][0], acc[i][1], acc[i][2], acc[i][3]);
        }
        float pl = acc[i][0] * av0 + acc[i][1] * av1 + acc[i][2] * av2 + acc[i][3] * av3;
        float pr = acc[i][0] * rv0 + acc[i][1] * rv1 + acc[i][2] * rv2 + acc[i][3] * rv3;
        pl += __shfl_xor_sync(0xffffffffu, pl, 1);
        pl += __shfl_xor_sync(0xffffffffu, pl, 2);
        pr += __shfl_xor_sync(0xffffffffu, pr, 1);
        pr += __shfl_xor_sync(0xffffffffu, pr, 2);
        if ((cx & 3) == 0 && row < NN) {
            g_el[((size_t)p * NN + row) * HEADS_ + head] = pl;
            g_er[((size_t)p * NN + row) * HEADS_ + head] = pr;
        }
    }
}

// ---------------- CSR build ----------------
__global__ void k_count(const int* __restrict__ edges) {
    int idx = blockIdx.x * blockDim.x + threadIdx.x;
    if (idx >= MM * EE) return;
    int p = idx / EE, e = idx - p * EE;
    int dst = edges[(size_t)p * 2 * EE + EE + e];
    atomicAdd(&g_deg[p * NN + dst], 1);
}

__global__ void k_scan() {   // single block, 1024 threads
    __shared__ int wsum[32];
    __shared__ int carry_s;
    int tid = threadIdx.x, lane = tid & 31, wid = tid >> 5;
    if (tid == 0) carry_s = 0;
    __syncthreads();
    for (int base = 0; base < NTASK; base += 1024) {
        int i = base + tid;
        int v = (i < NTASK) ? g_deg[i] : 0;
        int x = v;
#pragma unroll
        for (int off = 1; off < 32; off <<= 1) {
            int y = __shfl_up_sync(0xffffffffu, x, off);
            if (lane >= off) x += y;
        }
        if (lane == 31) wsum[wid] = x;
        __syncthreads();
        if (wid == 0) {
            int s = wsum[lane];
#pragma unroll
            for (int off = 1; off < 32; off <<= 1) {
                int y = __shfl_up_sync(0xffffffffu, s, off);
                if (lane >= off) s += y;
            }
            wsum[lane] = s;
        }
        __syncthreads();
        int prefix = carry_s + (wid ? wsum[wid - 1] : 0) + x - v;
        if (i < NTASK) g_off[i] = prefix;
        __syncthreads();
        if (tid == 0) carry_s += wsum[31];
        __syncthreads();
    }
}

__global__ void k_scatter(const int* __restrict__ edges) {
    int idx = blockIdx.x * blockDim.x + threadIdx.x;
    if (idx >= MM * EE) return;
    int p = idx / EE, e = idx - p * EE;
    const int* eb = edges + (size_t)p * 2 * EE;
    int src = eb[e], dst = eb[EE + e];
    int t = p * NN + dst;
    int pos = atomicAdd(&g_cur[t], 1);
    g_csr[g_off[t] + pos] = src;
}

// ---------------- fused edge softmax + aggregation + elu ----------------
// warp per (path, dst). Exact per-head max, online across chunks of CAP edges.
__global__ void k_agg() {
    __shared__ float sm_v[8][CAP * 8];
    __shared__ int   sm_src[8][CAP];
    int warp = threadIdx.x >> 5, lane = threadIdx.x & 31;
    int t = blockIdx.x * 8 + warp;
    if (t >= NTASK) return;
    int p = t / NN;
    int deg = g_deg[t];
    int base = g_off[t];

    if (deg == 0) {
        *(float4*)&g_z[(size_t)t * HD_ + lane * 4] = make_float4(0.f, 0.f, 0.f, 0.f);
        return;
    }

    int hA = lane & 7;       // head in (edge,head) layout
    int eSub = lane >> 3;    // 0..3
    int hB = lane >> 2;      // head owning this lane's acc dims

    float er_l = 0.f;
    if (lane < 8) er_l = g_er[(size_t)t * HEADS_ + lane];
    float er_hA = __shfl_sync(0xffffffffu, er_l, hA);

    float m = -1e30f, s = 0.f;
    float4 acc = make_float4(0.f, 0.f, 0.f, 0.f);

    for (int c0 = 0; c0 < deg; c0 += CAP) {
        int cn = min(CAP, deg - c0);
        // phase A: gather el, compute v, store to smem, chunk max per head
        float mc = -1e30f;
        for (int e = eSub; e < cn; e += 4) {
            int src = g_csr[base + c0 + e];
            if (hA == 0) sm_src[warp][e] = src;
            float v = g_el[((size_t)p * NN + src) * HEADS_ + hA] + er_hA;
            v = v > 0.f ? v : 0.2f * v;
            sm_v[warp][e * 8 + hA] = v;
            mc = fmaxf(mc, v);
        }
        mc = fmaxf(mc, __shfl_xor_sync(0xffffffffu, mc, 8));
        mc = fmaxf(mc, __shfl_xor_sync(0xffffffffu, mc, 16));
        float mNew = fmaxf(m, mc);
        float scale = __expf(m - mNew);       // 0 on first chunk (m=-1e30)
        // exp + chunk sum (lane-private smem slots, no sync needed yet)
        float cs = 0.f;
        for (int e = eSub; e < cn; e += 4) {
            float ex = __expf(sm_v[warp][e * 8 + hA] - mNew);
            sm_v[warp][e * 8 + hA] = ex;
            cs += ex;
        }
        cs += __shfl_xor_sync(0xffffffffu, cs, 8);
        cs += __shfl_xor_sync(0xffffffffu, cs, 16);
        s = s * scale + cs;
        m = mNew;
        float scaleB = __shfl_sync(0xffffffffu, scale, hB);
        acc.x *= scaleB; acc.y *= scaleB; acc.z *= scaleB; acc.w *= scaleB;
        __syncwarp();
        // phase B: feat gather + accumulate
#pragma unroll 4
        for (int e = 0; e < cn; e++) {
            int src = sm_src[warp][e];
            float ex = sm_v[warp][e * 8 + hB];
            float4 f = *(const float4*)&g_feat[((size_t)p * NN + src) * HD_ + lane * 4];
            acc.x += ex * f.x; acc.y += ex * f.y; acc.z += ex * f.z; acc.w += ex * f.w;
        }
        __syncwarp();
    }

    float sB = __shfl_sync(0xffffffffu, s, hB);
    float inv = 1.f / sB;
    float zx = acc.x * inv, zy = acc.y * inv, zz = acc.z * inv, zw = acc.w * inv;
    zx = zx > 0.f ? zx : expm1f(zx);
    zy = zy > 0.f ? zy : expm1f(zy);
    zz = zz > 0.f ? zz : expm1f(zz);
    zw = zw > 0.f ? zw : expm1f(zw);
    *(float4*)&g_z[(size_t)t * HD_ + lane * 4] = make_float4(zx, zy, zz, zw);
}

// ---------------- structure attention score: w = tanh(z@W1+b1)@w2 ----------------
// register-blocked like k_gemm: 32 rows x 128 cols, K=128
__global__ void k_w(const float* __restrict__ W1, const float* __restrict__ b1,
                    const float* __restrict__ w2) {
    __shared__ float  As[32][33];
    __shared__ float4 Bs[32][32];
    int mpath = blockIdx.y;
    int row0 = blockIdx.x * 32;
    int tid = threadIdx.x;
    int cx = tid & 31;
    int ry = tid >> 5;

    float4 b1v = *(const float4*)&b1[cx * 4];
    float acc[4][4];
#pragma unroll
    for (int i = 0; i < 4; i++) {
        acc[i][0] = b1v.x; acc[i][1] = b1v.y; acc[i][2] = b1v.z; acc[i][3] = b1v.w;
    }

    for (int kk = 0; kk < HD_; kk += 32) {
        {
            int r = tid >> 3;
            int k4 = (tid & 7) * 4;
            float4 av = make_float4(0.f, 0.f, 0.f, 0.f);
            if (row0 + r < NN)
                av = *(const float4*)&g_z[((size_t)mpath * NN + row0 + r) * HD_ + kk + k4];
            As[r][k4 + 0] = av.x; As[r][k4 + 1] = av.y;
            As[r][k4 + 2] = av.z; As[r][k4 + 3] = av.w;
        }
#pragma unroll
        for (int j = 0; j < 4; j++) {
            int q = tid + 256 * j;
            int bk = q >> 5, bc = q & 31;
            Bs[bk][bc] = *(const float4*)&W1[(size_t)(kk + bk) * HD_ + bc * 4];
        }
        __syncthreads();
#pragma unroll
        for (int k = 0; k < 32; k++) {
            float a0 = As[ry * 4 + 0][k];
            float a1 = As[ry * 4 + 1][k];
            float a2 = As[ry * 4 + 2][k];
            float a3 = As[ry * 4 + 3][k];
            float4 b = Bs[k][cx];
            acc[0][0] += a0 * b.x; acc[0][1] += a0 * b.y; acc[0][2] += a0 * b.z; acc[0][3] += a0 * b.w;
            acc[1][0] += a1 * b.x; acc[1][1] += a1 * b.y; acc[1][2] += a1 * b.z; acc[1][3] += a1 * b.w;
            acc[2][0] += a2 * b.x; acc[2][1] += a2 * b.y; acc[2][2] += a2 * b.z; acc[2][3] += a2 * b.w;
            acc[3][0] += a3 * b.x; acc[3][1] += a3 * b.y; acc[3][2] += a3 * b.z; acc[3][3] += a3 * b.w;
        }
        __syncthreads();
    }

    float4 w2v = *(const float4*)&w2[cx * 4];
#pragma unroll
    for (int i = 0; i < 4; i++) {
        int row = row0 + ry * 4 + i;
        float tsum = tanhf(acc[i][0]) * w2v.x + tanhf(acc[i][1]) * w2v.y +
                     tanhf(acc[i][2]) * w2v.z + tanhf(acc[i][3]) * w2v.w;
#pragma unroll
        for (int off = 16; off; off >>= 1)
            tsum += __shfl_xor_sync(0xffffffffu, tsum, off);
        if (cx == 0 && row < NN) g_w[(size_t)mpath * NN + row] = tsum;
    }
}

// ---------------- node softmax weighted sum ----------------
#define NODES_PER_BLK 64
__global__ void k_beta() {
    int j = threadIdx.x;
    int n0 = blockIdx.x * NODES_PER_BLK;
    float acc[MM] = {0.f, 0.f, 0.f};
    float wsl[MM] = {0.f, 0.f, 0.f};
    int n1 = n0 + NODES_PER_BLK;
    if (n1 > NN) n1 = NN;
    for (int n = n0; n < n1; n++) {
#pragma unroll
        for (int m = 0; m < MM; m++) {
            float pv = __expf(g_w[(size_t)m * NN + n]);
            acc[m] += pv * g_z[((size_t)m * NN + n) * HD_ + j];
            if (j == 0) wsl[m] += pv;
        }
    }
#pragma unroll
    for (int m = 0; m < MM; m++) {
        atomicAdd(&g_pz[m * HD_ + j], acc[m]);
        if (j == 0) atomicAdd(&g_wsum[m], wsl[m]);
    }
}

__global__ void k_final(const float* __restrict__ pred_w, const float* __restrict__ pred_b,
                        float* __restrict__ out) {
    int t = threadIdx.x;
    if (t < MM * OUT_) {
        int m = t / OUT_, o = t - m * OUT_;
        float inv = 1.f / g_wsum[m];
        float s = pred_b[o];
#pragma unroll 8
        for (int j = 0; j < HD_; j++)
            s += g_pz[m * HD_ + j] * inv * pred_w[(size_t)j * OUT_ + o];
        out[t] = s;
    }
}

// ---------------- launch ----------------
extern "C" void kernel_launch(void* const* d_in, const int* in_sizes, int n_in,
                              void* d_out, int out_size) {
    const float* h      = (const float*)d_in[0];
    const int*   edges  = (const int*)d_in[1];
    const float* fc_w   = (const float*)d_in[2];
    const float* attn_l = (const float*)d_in[3];
    const float* attn_r = (const float*)d_in[4];
    const float* sa_w1  = (const float*)d_in[5];
    const float* sa_b1  = (const float*)d_in[6];
    const float* sa_w2  = (const float*)d_in[7];
    const float* pred_w = (const float*)d_in[8];
    const float* pred_b = (const float*)d_in[9];
    float* out = (float*)d_out;

    void *pdeg, *pcur, *pwsum, *ppz;
    cudaGetSymbolAddress(&pdeg, g_deg);
    cudaGetSymbolAddress(&pcur, g_cur);
    cudaGetSymbolAddress(&pwsum, g_wsum);
    cudaGetSymbolAddress(&ppz, g_pz);
    cudaMemsetAsync(pdeg, 0, sizeof(int) * NTASK);
    cudaMemsetAsync(pcur, 0, sizeof(int) * NTASK);
    cudaMemsetAsync(pwsum, 0, sizeof(float) * MM);
    cudaMemsetAsync(ppz, 0, sizeof(float) * MM * HD_);

    dim3 gg((NN + 31) / 32, MM);
    k_gemm<<<gg, 256>>>(h, fc_w, attn_l, attn_r);

    int et = MM * EE;
    k_count<<<(et + 255) / 256, 256>>>(edges);
    k_scan<<<1, 1024>>>();
    k_scatter<<<(et + 255) / 256, 256>>>(edges);

    k_agg<<<(NTASK + 7) / 8, 256>>>();

    dim3 gw((NN + 31) / 32, MM);
    k_w<<<gw, 256>>>(sa_w1, sa_b1, sa_w2);
    k_beta<<<(NN + NODES_PER_BLK - 1) / NODES_PER_BLK, 128>>>();
    k_final<<<1, 32>>>(pred_w, pred_b, out);
}